// round 10
// baseline (speedup 1.0000x reference)
#include <cuda_runtime.h>
#include <cuda_bf16.h>
#include <cstdint>
#include <math.h>

#define T_STEPS 200
#define NB      256
#define H       512
#define CIN     128
#define G4      2048

// xproj tiling: 128x64, BK=32, 4 stages
#define XBM 128
#define XBN 64
// step tiling: 64(batch) x 64(gate rows), BK=32, 4 stages
#define SBM 64
#define LDT 40          // smem row stride (bf16 elems), 80B
#define GST 72

// ---- step kernel smem: stage block = Ahi,Alo,Bhi,Blo each 64*40*2=5120 -> 20480/stage
#define S_A(s,h)  ((s)*20480 + (h)*5120)
#define S_B(s,h)  ((s)*20480 + 10240 + (h)*5120)
#define S_G       81920
#define SSM_TOTAL (81920 + 64*GST*4)          // 100352
// ---- xproj smem: stage block = Ahi,Alo (10240 ea) + Bhi,Blo (5120 ea) = 30720/stage
#define X_A(s,h)  ((s)*30720 + (h)*10240)
#define X_B(s,h)  ((s)*30720 + 20480 + (h)*5120)
#define XSM_TOTAL (4*30720)                   // 122880

// ---------------- device scratch ----------------
__device__ __nv_bfloat16 g_wih_hi0[G4*CIN], g_wih_lo0[G4*CIN];
__device__ __nv_bfloat16 g_wih_hi1[G4*H],   g_wih_lo1[G4*H];
__device__ __nv_bfloat16 g_whh_hi0[G4*H],   g_whh_lo0[G4*H];
__device__ __nv_bfloat16 g_whh_hi1[G4*H],   g_whh_lo1[G4*H];
__device__ __nv_bfloat16 g_h_hi0[(size_t)T_STEPS*NB*H], g_h_lo0[(size_t)T_STEPS*NB*H];
__device__ __nv_bfloat16 g_h_hi1[(size_t)T_STEPS*NB*H], g_h_lo1[(size_t)T_STEPS*NB*H];
__device__ __nv_bfloat16 g_x_hi[(size_t)T_STEPS*NB*CIN], g_x_lo[(size_t)T_STEPS*NB*CIN];
__device__ float g_xp[(size_t)T_STEPS*NB*G4];
__device__ float g_c0[NB*H], g_c1[NB*H];
__device__ float g_base[NB*H];

// ---------------- helpers ----------------
__device__ __forceinline__ uint32_t smem_u32(const void* p) {
    return (uint32_t)__cvta_generic_to_shared(p);
}
__device__ __forceinline__ void ldm_x4(uint32_t& r0, uint32_t& r1, uint32_t& r2, uint32_t& r3,
                                       uint32_t addr) {
    asm volatile("ldmatrix.sync.aligned.m8n8.x4.shared.b16 {%0,%1,%2,%3}, [%4];"
                 : "=r"(r0), "=r"(r1), "=r"(r2), "=r"(r3) : "r"(addr));
}
__device__ __forceinline__ void mma_bf16(float* c, const uint32_t* a, uint32_t b0, uint32_t b1) {
    asm volatile("mma.sync.aligned.m16n8k16.row.col.f32.bf16.bf16.f32 "
                 "{%0,%1,%2,%3}, {%4,%5,%6,%7}, {%8,%9}, {%0,%1,%2,%3};"
                 : "+f"(c[0]), "+f"(c[1]), "+f"(c[2]), "+f"(c[3])
                 : "r"(a[0]), "r"(a[1]), "r"(a[2]), "r"(a[3]), "r"(b0), "r"(b1));
}
__device__ __forceinline__ void cpa16(uint32_t dst, const void* src) {
    asm volatile("cp.async.cg.shared.global [%0], [%1], 16;" :: "r"(dst), "l"(src));
}
__device__ __forceinline__ void cpa_commit() { asm volatile("cp.async.commit_group;"); }
__device__ __forceinline__ void cpa_wait0()  { asm volatile("cp.async.wait_group 0;"); }
__device__ __forceinline__ void cpa_wait1()  { asm volatile("cp.async.wait_group 1;"); }
__device__ __forceinline__ void cpa_wait2()  { asm volatile("cp.async.wait_group 2;"); }
__device__ __forceinline__ void cpa_wait_tail(int c, int NC) {
    if (c < NC - 2)      cpa_wait2();
    else if (c == NC - 2) cpa_wait1();
    else                  cpa_wait0();
}
__device__ __forceinline__ float sigf(float x) { return 1.f / (1.f + expf(-x)); }

// ---------------- init ----------------
__global__ void zero_kernel(float* __restrict__ out, int out_size) {
    int i = blockIdx.x * blockDim.x + threadIdx.x;
    int s = gridDim.x * blockDim.x;
    for (int k = i; k < out_size; k += s) out[k] = 0.f;
    for (int k = i; k < NB * H; k += s) { g_c0[k] = 0.f; g_c1[k] = 0.f; }
}

// ---------------- fp32 -> bf16 hi/lo ----------------
__global__ void conv_w(const float* __restrict__ src, int which, int n) {
    int i = blockIdx.x * blockDim.x + threadIdx.x;
    if (i >= n) return;
    float v = src[i];
    __nv_bfloat16 h = __float2bfloat16(v);
    __nv_bfloat16 l = __float2bfloat16(v - __bfloat162float(h));
    switch (which) {
        case 0: g_wih_hi0[i] = h; g_wih_lo0[i] = l; break;
        case 1: g_whh_hi0[i] = h; g_whh_lo0[i] = l; break;
        case 2: g_wih_hi1[i] = h; g_wih_lo1[i] = l; break;
        case 3: g_whh_hi1[i] = h; g_whh_lo1[i] = l; break;
    }
}
__global__ void conv_x(const float* __restrict__ prop) {
    int i = blockIdx.x * blockDim.x + threadIdx.x;
    if (i >= T_STEPS * NB * CIN) return;
    int k = i & (CIN - 1);
    int m = i >> 7;
    int b = m & (NB - 1), t = m >> 8;
    float v = prop[((size_t)b * T_STEPS + t) * CIN + k];
    __nv_bfloat16 h = __float2bfloat16(v);
    g_x_hi[i] = h;
    g_x_lo[i] = __float2bfloat16(v - __bfloat162float(h));
}

// ---------------- xproj GEMM: 128x64 tile, 4-stage cp.async pipeline --------
__global__ void __launch_bounds__(256) xproj_mma(int K, int layer,
                                                 const float* __restrict__ bih,
                                                 const float* __restrict__ bhh) {
    extern __shared__ char smem[];
    __shared__ float sbias[XBN];
    const uint32_t sb = smem_u32(smem);
    const int tid  = threadIdx.x;
    const int lane = tid & 31;
    const int warp = tid >> 5;
    const int wm = warp & 3;            // 4 m-warps of 32 rows
    const int wn = warp >> 2;           // 2 n-warps of 32 cols

    const int m0 = blockIdx.y * XBM;
    const int n0 = blockIdx.x * XBN;
    const __nv_bfloat16* Aptr_hi = layer ? g_h_hi0 : g_x_hi;
    const __nv_bfloat16* Aptr_lo = layer ? g_h_lo0 : g_x_lo;
    const __nv_bfloat16* Bptr_hi = layer ? g_wih_hi1 : g_wih_hi0;
    const __nv_bfloat16* Bptr_lo = layer ? g_wih_lo1 : g_wih_lo0;
    if (tid < XBN) sbias[tid] = bih[n0 + tid] + bhh[n0 + tid];

    float acc[2][4][4] = {};
    const int NC = K >> 5;

    const int brow_ld = tid >> 2, bseg_ld = (tid & 3) * 8;

    const int acol = (lane >> 4) * 8;
    const int arow_f = wm * 32 + (lane & 15);
    const int brow_f = ((lane >> 4) << 3) + (lane & 7);
    const int bcol_f = ((lane >> 3) & 1) * 8;

    // prologue: chunks 0..2 -> stages 0..2
    #pragma unroll
    for (int pc = 0; pc < 3; pc++) {
        const int c0 = pc << 5;
        #pragma unroll
        for (int i = 0; i < 2; i++) {
            int idx = tid + i * 256; int r = idx >> 2, sg = (idx & 3) * 8;
            size_t ga = (size_t)(m0 + r) * K + c0 + sg;
            uint32_t so = (uint32_t)(r * LDT + sg) * 2;
            cpa16(sb + X_A(pc,0) + so, Aptr_hi + ga);
            cpa16(sb + X_A(pc,1) + so, Aptr_lo + ga);
        }
        size_t gb = (size_t)(n0 + brow_ld) * K + c0 + bseg_ld;
        uint32_t so = (uint32_t)(brow_ld * LDT + bseg_ld) * 2;
        cpa16(sb + X_B(pc,0) + so, Bptr_hi + gb);
        cpa16(sb + X_B(pc,1) + so, Bptr_lo + gb);
        cpa_commit();
    }

    for (int c = 0; c < NC; c++) {
        const int st = c & 3;
        cpa_wait_tail(c, NC);
        __syncthreads();
        if (c + 3 < NC) {
            const int ns = (c + 3) & 3;
            const int c0 = (c + 3) << 5;
            #pragma unroll
            for (int i = 0; i < 2; i++) {
                int idx = tid + i * 256; int r = idx >> 2, sg = (idx & 3) * 8;
                size_t ga = (size_t)(m0 + r) * K + c0 + sg;
                uint32_t so = (uint32_t)(r * LDT + sg) * 2;
                cpa16(sb + X_A(ns,0) + so, Aptr_hi + ga);
                cpa16(sb + X_A(ns,1) + so, Aptr_lo + ga);
            }
            size_t gb = (size_t)(n0 + brow_ld) * K + c0 + bseg_ld;
            uint32_t so = (uint32_t)(brow_ld * LDT + bseg_ld) * 2;
            cpa16(sb + X_B(ns,0) + so, Bptr_hi + gb);
            cpa16(sb + X_B(ns,1) + so, Bptr_lo + gb);
            cpa_commit();
        }

        const uint32_t aH = sb + X_A(st,0) + (uint32_t)(arow_f * LDT + acol) * 2;
        const uint32_t aL = sb + X_A(st,1) + (uint32_t)(arow_f * LDT + acol) * 2;
        const uint32_t bH0 = sb + X_B(st,0) + (uint32_t)((wn * 32 + brow_f) * LDT + bcol_f) * 2;
        const uint32_t bL0 = sb + X_B(st,1) + (uint32_t)((wn * 32 + brow_f) * LDT + bcol_f) * 2;

        #pragma unroll
        for (int kk = 0; kk < 2; kk++) {
            const uint32_t koff = (uint32_t)(kk * 32);
            uint32_t a_hi[2][4], a_lo[2][4];
            #pragma unroll
            for (int mt = 0; mt < 2; mt++) {
                ldm_x4(a_hi[mt][0], a_hi[mt][1], a_hi[mt][2], a_hi[mt][3],
                       aH + mt * 16 * LDT * 2 + koff);
                ldm_x4(a_lo[mt][0], a_lo[mt][1], a_lo[mt][2], a_lo[mt][3],
                       aL + mt * 16 * LDT * 2 + koff);
            }
            uint32_t b_hi[2][4], b_lo[2][4];
            #pragma unroll
            for (int nf2 = 0; nf2 < 2; nf2++) {
                ldm_x4(b_hi[nf2][0], b_hi[nf2][1], b_hi[nf2][2], b_hi[nf2][3],
                       bH0 + nf2 * 16 * LDT * 2 + koff);
                ldm_x4(b_lo[nf2][0], b_lo[nf2][1], b_lo[nf2][2], b_lo[nf2][3],
                       bL0 + nf2 * 16 * LDT * 2 + koff);
            }
            #pragma unroll
            for (int mt = 0; mt < 2; mt++)
                #pragma unroll
                for (int nf = 0; nf < 4; nf++) {
                    int n2 = nf >> 1, rp = (nf & 1) * 2;
                    mma_bf16(acc[mt][nf], a_hi[mt], b_hi[n2][rp], b_hi[n2][rp + 1]);
                    mma_bf16(acc[mt][nf], a_hi[mt], b_lo[n2][rp], b_lo[n2][rp + 1]);
                    mma_bf16(acc[mt][nf], a_lo[mt], b_hi[n2][rp], b_hi[n2][rp + 1]);
                }
        }
    }
    __syncthreads();

    #pragma unroll
    for (int mt = 0; mt < 2; mt++) {
        int r = m0 + wm * 32 + mt * 16 + (lane >> 2);
        #pragma unroll
        for (int nf = 0; nf < 4; nf++) {
            int nn = wn * 32 + nf * 8 + (lane & 3) * 2;
            float b0v = sbias[nn], b1v = sbias[nn + 1];
            int n = n0 + nn;
            g_xp[(size_t)r * G4 + n]           = acc[mt][nf][0] + b0v;
            g_xp[(size_t)r * G4 + n + 1]       = acc[mt][nf][1] + b1v;
            g_xp[(size_t)(r + 8) * G4 + n]     = acc[mt][nf][2] + b0v;
            g_xp[(size_t)(r + 8) * G4 + n + 1] = acc[mt][nf][3] + b1v;
        }
    }
}

// ---------------- fused LSTM step, 4-stage cp.async pipeline ----------------
// grid (32, 4): j0 = bx*16 (64 gate rows), b0 = by*64
__global__ void __launch_bounds__(256) lstm_step_mma(int t, int layer) {
    extern __shared__ char smem[];
    const uint32_t sb = smem_u32(smem);
    const int tid  = threadIdx.x;
    const int lane = tid & 31;
    const int warp = tid >> 5;
    const int wm = warp >> 2;           // 2 m-warps of 32
    const int wn = warp & 3;            // 4 n-warps of 16
    const int j0 = blockIdx.x * 16;
    const int b0 = blockIdx.y * 64;

    __nv_bfloat16* hb_hi = layer ? g_h_hi1 : g_h_hi0;
    __nv_bfloat16* hb_lo = layer ? g_h_lo1 : g_h_lo0;
    const __nv_bfloat16* Whi = layer ? g_whh_hi1 : g_whh_hi0;
    const __nv_bfloat16* Wlo = layer ? g_whh_lo1 : g_whh_lo0;
    float* cst = layer ? g_c1 : g_c0;
    float* gst = (float*)(smem + S_G);

    float acc[2][2][4] = {};

    if (t > 0) {
        const __nv_bfloat16* hp_hi = hb_hi + (size_t)(t - 1) * NB * H;
        const __nv_bfloat16* hp_lo = hb_lo + (size_t)(t - 1) * NB * H;

        const int lrow = tid >> 2;
        const int lseg = (tid & 3) * 8;
        const int browg = (lrow >> 4) * H + j0 + (lrow & 15);

        const int acol = (lane >> 4) * 8;
        const int arow_f = wm * 32 + (lane & 15);
        const int brow_f = wn * 16 + ((lane >> 4) << 3) + (lane & 7);
        const int bcol_f = ((lane >> 3) & 1) * 8;

        // prologue: chunks 0..2 -> stages 0..2
        #pragma unroll
        for (int pc = 0; pc < 3; pc++) {
            const int c0 = pc << 5;
            size_t ga = (size_t)(b0 + lrow) * H + c0 + lseg;
            size_t gb = (size_t)browg * H + c0 + lseg;
            uint32_t so = (uint32_t)(lrow * LDT + lseg) * 2;
            cpa16(sb + S_A(pc,0) + so, hp_hi + ga);
            cpa16(sb + S_A(pc,1) + so, hp_lo + ga);
            cpa16(sb + S_B(pc,0) + so, Whi + gb);
            cpa16(sb + S_B(pc,1) + so, Wlo + gb);
            cpa_commit();
        }

        for (int c = 0; c < 16; c++) {
            const int st = c & 3;
            cpa_wait_tail(c, 16);
            __syncthreads();
            if (c + 3 < 16) {
                const int ns = (c + 3) & 3;
                const int c0 = (c + 3) << 5;
                size_t ga = (size_t)(b0 + lrow) * H + c0 + lseg;
                size_t gb = (size_t)browg * H + c0 + lseg;
                uint32_t so = (uint32_t)(lrow * LDT + lseg) * 2;
                cpa16(sb + S_A(ns,0) + so, hp_hi + ga);
                cpa16(sb + S_A(ns,1) + so, hp_lo + ga);
                cpa16(sb + S_B(ns,0) + so, Whi + gb);
                cpa16(sb + S_B(ns,1) + so, Wlo + gb);
                cpa_commit();
            }

            const uint32_t aH = sb + S_A(st,0) + (uint32_t)(arow_f * LDT + acol) * 2;
            const uint32_t aL = sb + S_A(st,1) + (uint32_t)(arow_f * LDT + acol) * 2;
            const uint32_t bH = sb + S_B(st,0) + (uint32_t)(brow_f * LDT + bcol_f) * 2;
            const uint32_t bL = sb + S_B(st,1) + (uint32_t)(brow_f * LDT + bcol_f) * 2;

            #pragma unroll
            for (int kk = 0; kk < 2; kk++) {
                const uint32_t koff = (uint32_t)(kk * 32);
                uint32_t a_hi[2][4], a_lo[2][4];
                #pragma unroll
                for (int mt = 0; mt < 2; mt++) {
                    ldm_x4(a_hi[mt][0], a_hi[mt][1], a_hi[mt][2], a_hi[mt][3],
                           aH + mt * 16 * LDT * 2 + koff);
                    ldm_x4(a_lo[mt][0], a_lo[mt][1], a_lo[mt][2], a_lo[mt][3],
                           aL + mt * 16 * LDT * 2 + koff);
                }
                uint32_t b_hi[4], b_lo[4];
                ldm_x4(b_hi[0], b_hi[1], b_hi[2], b_hi[3], bH + koff);
                ldm_x4(b_lo[0], b_lo[1], b_lo[2], b_lo[3], bL + koff);
                #pragma unroll
                for (int mt = 0; mt < 2; mt++)
                    #pragma unroll
                    for (int nt = 0; nt < 2; nt++) {
                        mma_bf16(acc[mt][nt], a_hi[mt], b_hi[nt * 2], b_hi[nt * 2 + 1]);
                        mma_bf16(acc[mt][nt], a_hi[mt], b_lo[nt * 2], b_lo[nt * 2 + 1]);
                        mma_bf16(acc[mt][nt], a_lo[mt], b_hi[nt * 2], b_hi[nt * 2 + 1]);
                    }
            }
        }
    }

    // stage gates
    #pragma unroll
    for (int mt = 0; mt < 2; mt++) {
        int r = wm * 32 + mt * 16 + (lane >> 2);
        #pragma unroll
        for (int nt = 0; nt < 2; nt++) {
            int cc = wn * 16 + nt * 8 + (lane & 3) * 2;
            gst[r * GST + cc]           = acc[mt][nt][0];
            gst[r * GST + cc + 1]       = acc[mt][nt][1];
            gst[(r + 8) * GST + cc]     = acc[mt][nt][2];
            gst[(r + 8) * GST + cc + 1] = acc[mt][nt][3];
        }
    }
    __syncthreads();

    // fused cell update (vectorized: one (b, 4-j) group per thread)
    {
        __nv_bfloat16* ho_hi = hb_hi + (size_t)t * NB * H;
        __nv_bfloat16* ho_lo = hb_lo + (size_t)t * NB * H;
        const float* xp = g_xp + (size_t)t * NB * G4;
        const bool wbase = (layer == 1) && (t == T_STEPS - 1);

        int bb = tid >> 2, jg = (tid & 3) * 4;
        int b  = b0 + bb;
        const float* xr = xp + (size_t)b * G4 + j0 + jg;
        float4 xi = *(const float4*)(xr + 0 * H);
        float4 xf = *(const float4*)(xr + 1 * H);
        float4 xg = *(const float4*)(xr + 2 * H);
        float4 xo = *(const float4*)(xr + 3 * H);
        const float* g = &gst[bb * GST];
        float gi[4] = { g[jg] + xi.x, g[jg + 1] + xi.y, g[jg + 2] + xi.z, g[jg + 3] + xi.w };
        float gf[4] = { g[16 + jg] + xf.x, g[17 + jg] + xf.y, g[18 + jg] + xf.z, g[19 + jg] + xf.w };
        float gg[4] = { g[32 + jg] + xg.x, g[33 + jg] + xg.y, g[34 + jg] + xg.z, g[35 + jg] + xg.w };
        float go[4] = { g[48 + jg] + xo.x, g[49 + jg] + xo.y, g[50 + jg] + xo.z, g[51 + jg] + xo.w };

        size_t idx = (size_t)b * H + j0 + jg;
        float4 cold = *(const float4*)(cst + idx);
        float cn[4], hv[4];
        const float* cop = (const float*)&cold;
        __nv_bfloat16 hhv[4], hlv[4];
        #pragma unroll
        for (int q = 0; q < 4; q++) {
            float iv = sigf(gi[q]), fv = sigf(gf[q]), gv = tanhf(gg[q]), ov = sigf(go[q]);
            cn[q] = fv * cop[q] + iv * gv;
            hv[q] = ov * tanhf(cn[q]);
            hhv[q] = __float2bfloat16(hv[q]);
            hlv[q] = __float2bfloat16(hv[q] - __bfloat162float(hhv[q]));
        }
        *(float4*)(cst + idx) = *(float4*)cn;
        *(uint2*)&ho_hi[idx] = *(uint2*)hhv;
        *(uint2*)&ho_lo[idx] = *(uint2*)hlv;
        if (wbase) *(float4*)(g_base + idx) = *(float4*)hv;
    }
}

// ---------------- heads ----------------
__global__ void heads_kernel(const float* __restrict__ cls_W, const float* __restrict__ cls_b,
                             const float* __restrict__ bbox_W, const float* __restrict__ bbox_b,
                             float* __restrict__ out) {
    __shared__ float base[H];
    int b = blockIdx.x;
    const float* src = g_base + (size_t)b * H;
    for (int k = threadIdx.x; k < H; k += blockDim.x) base[k] = src[k];
    __syncthreads();
    for (int o = threadIdx.x; o < 42; o += blockDim.x) {
        const float* w = (o < 40) ? &cls_W[o * H] : &bbox_W[(o - 40) * H];
        float s = (o < 40) ? cls_b[o] : bbox_b[o - 40];
        #pragma unroll 8
        for (int k = 0; k < H; k++) s += base[k] * w[k];
        if (o < 40) out[b * 40 + o] = s;
        else        out[NB * 40 + b * 2 + (o - 40)] = s;
    }
}

extern "C" void kernel_launch(void* const* d_in, const int* in_sizes, int n_in,
                              void* d_out, int out_size) {
    const float* proposals = (const float*)d_in[2];
    const float* Wih0 = (const float*)d_in[4];
    const float* Whh0 = (const float*)d_in[5];
    const float* bih0 = (const float*)d_in[6];
    const float* bhh0 = (const float*)d_in[7];
    const float* Wih1 = (const float*)d_in[8];
    const float* Whh1 = (const float*)d_in[9];
    const float* bih1 = (const float*)d_in[10];
    const float* bhh1 = (const float*)d_in[11];
    const float* cls_W  = (const float*)d_in[12];
    const float* cls_b  = (const float*)d_in[13];
    const float* bbox_W = (const float*)d_in[14];
    const float* bbox_b = (const float*)d_in[15];
    float* out = (float*)d_out;

    cudaFuncSetAttribute(xproj_mma, cudaFuncAttributeMaxDynamicSharedMemorySize, XSM_TOTAL);
    cudaFuncSetAttribute(lstm_step_mma, cudaFuncAttributeMaxDynamicSharedMemorySize, SSM_TOTAL);

    zero_kernel<<<256, 256>>>(out, out_size);

    conv_w<<<(G4 * CIN + 255) / 256, 256>>>(Wih0, 0, G4 * CIN);
    conv_w<<<(G4 * H + 255) / 256, 256>>>(Whh0, 1, G4 * H);
    conv_w<<<(G4 * H + 255) / 256, 256>>>(Wih1, 2, G4 * H);
    conv_w<<<(G4 * H + 255) / 256, 256>>>(Whh1, 3, G4 * H);
    conv_x<<<(T_STEPS * NB * CIN + 255) / 256, 256>>>(proposals);

    dim3 gx(G4 / XBN, (T_STEPS * NB) / XBM);   // (32, 400)
    dim3 gs(H / 16, NB / SBM);                 // (32, 4)

    xproj_mma<<<gx, 256, XSM_TOTAL>>>(CIN, 0, bih0, bhh0);
    for (int t = 0; t < T_STEPS; t++)
        lstm_step_mma<<<gs, 256, SSM_TOTAL>>>(t, 0);

    xproj_mma<<<gx, 256, XSM_TOTAL>>>(H, 1, bih1, bhh1);
    for (int t = 0; t < T_STEPS; t++)
        lstm_step_mma<<<gs, 256, SSM_TOTAL>>>(t, 1);

    heads_kernel<<<NB, 64>>>(cls_W, cls_b, bbox_W, bbox_b, out);
}

// round 11
// speedup vs baseline: 1.0384x; 1.0384x over previous
#include <cuda_runtime.h>
#include <cuda_bf16.h>
#include <cstdint>
#include <math.h>

#define T_STEPS 200
#define NB      256
#define H       512
#define CIN     128
#define G4      2048
#define NBH     (NB*H)

// xproj tiling: 128x64, BK=32, 4 stages
#define XBM 128
#define XBN 64
#define LDT 40          // smem row stride (bf16 elems), 80B
#define GST 72

// ---- step kernel smem (2-stage): Ahi,Alo,Bhi,Blo each 64*40*2=5120 -> 20480/stage
#define S_A(s,h)  ((s)*20480 + (h)*5120)
#define S_B(s,h)  ((s)*20480 + 10240 + (h)*5120)
#define S_G       40960
#define SSM_TOTAL (40960 + 64*GST*4)          // 59392
// ---- xproj smem (4-stage)
#define X_A(s,h)  ((s)*30720 + (h)*10240)
#define X_B(s,h)  ((s)*30720 + 20480 + (h)*5120)
#define XSM_TOTAL (4*30720)                   // 122880

// ---------------- device scratch ----------------
__device__ __nv_bfloat16 g_wih_hi0[G4*CIN], g_wih_lo0[G4*CIN];
__device__ __nv_bfloat16 g_whh_hi0[G4*H],   g_whh_lo0[G4*H];
__device__ __nv_bfloat16 g_w1c_hi[(size_t)G4*1024], g_w1c_lo[(size_t)G4*1024]; // [Wih1|Whh1]
__device__ __nv_bfloat16 g_h_hi0[(size_t)T_STEPS*NBH], g_h_lo0[(size_t)T_STEPS*NBH];
__device__ __nv_bfloat16 g_h_hi1[(size_t)T_STEPS*NBH], g_h_lo1[(size_t)T_STEPS*NBH];
__device__ __nv_bfloat16 g_x_hi[(size_t)T_STEPS*NB*CIN], g_x_lo[(size_t)T_STEPS*NB*CIN];
__device__ float g_xp[(size_t)T_STEPS*NB*G4];
__device__ float g_c0[NBH], g_c1[NBH];
__device__ float g_base[NBH];

// ---------------- helpers ----------------
__device__ __forceinline__ uint32_t smem_u32(const void* p) {
    return (uint32_t)__cvta_generic_to_shared(p);
}
__device__ __forceinline__ void ldm_x4(uint32_t& r0, uint32_t& r1, uint32_t& r2, uint32_t& r3,
                                       uint32_t addr) {
    asm volatile("ldmatrix.sync.aligned.m8n8.x4.shared.b16 {%0,%1,%2,%3}, [%4];"
                 : "=r"(r0), "=r"(r1), "=r"(r2), "=r"(r3) : "r"(addr));
}
__device__ __forceinline__ void mma_bf16(float* c, const uint32_t* a, uint32_t b0, uint32_t b1) {
    asm volatile("mma.sync.aligned.m16n8k16.row.col.f32.bf16.bf16.f32 "
                 "{%0,%1,%2,%3}, {%4,%5,%6,%7}, {%8,%9}, {%0,%1,%2,%3};"
                 : "+f"(c[0]), "+f"(c[1]), "+f"(c[2]), "+f"(c[3])
                 : "r"(a[0]), "r"(a[1]), "r"(a[2]), "r"(a[3]), "r"(b0), "r"(b1));
}
__device__ __forceinline__ void cpa16(uint32_t dst, const void* src) {
    asm volatile("cp.async.cg.shared.global [%0], [%1], 16;" :: "r"(dst), "l"(src));
}
__device__ __forceinline__ void cpa_commit() { asm volatile("cp.async.commit_group;"); }
__device__ __forceinline__ void cpa_wait0()  { asm volatile("cp.async.wait_group 0;"); }
__device__ __forceinline__ void cpa_wait1()  { asm volatile("cp.async.wait_group 1;"); }
__device__ __forceinline__ void cpa_wait2()  { asm volatile("cp.async.wait_group 2;"); }
__device__ __forceinline__ void cpa_wait_tail(int c, int NC) {
    if (c < NC - 2)      cpa_wait2();
    else if (c == NC - 2) cpa_wait1();
    else                  cpa_wait0();
}
__device__ __forceinline__ float sigf(float x) { return 1.f / (1.f + expf(-x)); }

// ---------------- init ----------------
__global__ void zero_kernel(float* __restrict__ out, int out_size) {
    int i = blockIdx.x * blockDim.x + threadIdx.x;
    int s = gridDim.x * blockDim.x;
    for (int k = i; k < out_size; k += s) out[k] = 0.f;
    for (int k = i; k < NBH; k += s) { g_c0[k] = 0.f; g_c1[k] = 0.f; }
}

// ---------------- fp32 -> bf16 hi/lo ----------------
__global__ void conv_w(const float* __restrict__ src, int which, int n) {
    int i = blockIdx.x * blockDim.x + threadIdx.x;
    if (i >= n) return;
    float v = src[i];
    __nv_bfloat16 h = __float2bfloat16(v);
    __nv_bfloat16 l = __float2bfloat16(v - __bfloat162float(h));
    if (which == 0) { g_wih_hi0[i] = h; g_wih_lo0[i] = l; }
    else            { g_whh_hi0[i] = h; g_whh_lo0[i] = l; }
}
// packed layer-1 weights: row r (0..2047), k (0..1023): k<512 -> Wih1, else Whh1
__global__ void conv_w1(const float* __restrict__ Wih1, const float* __restrict__ Whh1) {
    int i = blockIdx.x * blockDim.x + threadIdx.x;
    if (i >= G4 * 1024) return;
    int r = i >> 10, k = i & 1023;
    float v = (k < 512) ? Wih1[(size_t)r * 512 + k] : Whh1[(size_t)r * 512 + (k - 512)];
    __nv_bfloat16 h = __float2bfloat16(v);
    g_w1c_hi[i] = h;
    g_w1c_lo[i] = __float2bfloat16(v - __bfloat162float(h));
}
__global__ void conv_x(const float* __restrict__ prop) {
    int i = blockIdx.x * blockDim.x + threadIdx.x;
    if (i >= T_STEPS * NB * CIN) return;
    int k = i & (CIN - 1);
    int m = i >> 7;
    int b = m & (NB - 1), t = m >> 8;
    float v = prop[((size_t)b * T_STEPS + t) * CIN + k];
    __nv_bfloat16 h = __float2bfloat16(v);
    g_x_hi[i] = h;
    g_x_lo[i] = __float2bfloat16(v - __bfloat162float(h));
}

// ---------------- xproj GEMM (layer 0 only): 128x64 tile, 4-stage -----------
__global__ void __launch_bounds__(256) xproj_mma(int K,
                                                 const float* __restrict__ bih,
                                                 const float* __restrict__ bhh) {
    extern __shared__ char smem[];
    __shared__ float sbias[XBN];
    const uint32_t sb = smem_u32(smem);
    const int tid  = threadIdx.x;
    const int lane = tid & 31;
    const int warp = tid >> 5;
    const int wm = warp & 3;
    const int wn = warp >> 2;

    const int m0 = blockIdx.y * XBM;
    const int n0 = blockIdx.x * XBN;
    const __nv_bfloat16* Aptr_hi = g_x_hi;
    const __nv_bfloat16* Aptr_lo = g_x_lo;
    const __nv_bfloat16* Bptr_hi = g_wih_hi0;
    const __nv_bfloat16* Bptr_lo = g_wih_lo0;
    if (tid < XBN) sbias[tid] = bih[n0 + tid] + bhh[n0 + tid];

    float acc[2][4][4] = {};
    const int NC = K >> 5;

    const int brow_ld = tid >> 2, bseg_ld = (tid & 3) * 8;
    const int acol = (lane >> 4) * 8;
    const int arow_f = wm * 32 + (lane & 15);
    const int brow_f = ((lane >> 4) << 3) + (lane & 7);
    const int bcol_f = ((lane >> 3) & 1) * 8;

    #pragma unroll
    for (int pc = 0; pc < 3; pc++) {
        if (pc < NC) {
            const int c0 = pc << 5;
            #pragma unroll
            for (int i = 0; i < 2; i++) {
                int idx = tid + i * 256; int r = idx >> 2, sg = (idx & 3) * 8;
                size_t ga = (size_t)(m0 + r) * K + c0 + sg;
                uint32_t so = (uint32_t)(r * LDT + sg) * 2;
                cpa16(sb + X_A(pc,0) + so, Aptr_hi + ga);
                cpa16(sb + X_A(pc,1) + so, Aptr_lo + ga);
            }
            size_t gb = (size_t)(n0 + brow_ld) * K + (pc << 5) + bseg_ld;
            uint32_t so = (uint32_t)(brow_ld * LDT + bseg_ld) * 2;
            cpa16(sb + X_B(pc,0) + so, Bptr_hi + gb);
            cpa16(sb + X_B(pc,1) + so, Bptr_lo + gb);
        }
        cpa_commit();
    }

    for (int c = 0; c < NC; c++) {
        const int st = c & 3;
        cpa_wait_tail(c, NC);
        __syncthreads();
        {
            const int ns = (c + 3) & 3;
            const int c0 = (c + 3) << 5;
            if (c + 3 < NC) {
                #pragma unroll
                for (int i = 0; i < 2; i++) {
                    int idx = tid + i * 256; int r = idx >> 2, sg = (idx & 3) * 8;
                    size_t ga = (size_t)(m0 + r) * K + c0 + sg;
                    uint32_t so = (uint32_t)(r * LDT + sg) * 2;
                    cpa16(sb + X_A(ns,0) + so, Aptr_hi + ga);
                    cpa16(sb + X_A(ns,1) + so, Aptr_lo + ga);
                }
                size_t gb = (size_t)(n0 + brow_ld) * K + c0 + bseg_ld;
                uint32_t so = (uint32_t)(brow_ld * LDT + bseg_ld) * 2;
                cpa16(sb + X_B(ns,0) + so, Bptr_hi + gb);
                cpa16(sb + X_B(ns,1) + so, Bptr_lo + gb);
            }
            cpa_commit();
        }

        const uint32_t aH = sb + X_A(st,0) + (uint32_t)(arow_f * LDT + acol) * 2;
        const uint32_t aL = sb + X_A(st,1) + (uint32_t)(arow_f * LDT + acol) * 2;
        const uint32_t bH0 = sb + X_B(st,0) + (uint32_t)((wn * 32 + brow_f) * LDT + bcol_f) * 2;
        const uint32_t bL0 = sb + X_B(st,1) + (uint32_t)((wn * 32 + brow_f) * LDT + bcol_f) * 2;

        #pragma unroll
        for (int kk = 0; kk < 2; kk++) {
            const uint32_t koff = (uint32_t)(kk * 32);
            uint32_t a_hi[2][4], a_lo[2][4];
            #pragma unroll
            for (int mt = 0; mt < 2; mt++) {
                ldm_x4(a_hi[mt][0], a_hi[mt][1], a_hi[mt][2], a_hi[mt][3],
                       aH + mt * 16 * LDT * 2 + koff);
                ldm_x4(a_lo[mt][0], a_lo[mt][1], a_lo[mt][2], a_lo[mt][3],
                       aL + mt * 16 * LDT * 2 + koff);
            }
            uint32_t b_hi[2][4], b_lo[2][4];
            #pragma unroll
            for (int nf2 = 0; nf2 < 2; nf2++) {
                ldm_x4(b_hi[nf2][0], b_hi[nf2][1], b_hi[nf2][2], b_hi[nf2][3],
                       bH0 + nf2 * 16 * LDT * 2 + koff);
                ldm_x4(b_lo[nf2][0], b_lo[nf2][1], b_lo[nf2][2], b_lo[nf2][3],
                       bL0 + nf2 * 16 * LDT * 2 + koff);
            }
            #pragma unroll
            for (int mt = 0; mt < 2; mt++)
                #pragma unroll
                for (int nf = 0; nf < 4; nf++) {
                    int n2 = nf >> 1, rp = (nf & 1) * 2;
                    mma_bf16(acc[mt][nf], a_hi[mt], b_hi[n2][rp], b_hi[n2][rp + 1]);
                    mma_bf16(acc[mt][nf], a_hi[mt], b_lo[n2][rp], b_lo[n2][rp + 1]);
                    mma_bf16(acc[mt][nf], a_lo[mt], b_hi[n2][rp], b_hi[n2][rp + 1]);
                }
        }
    }
    __syncthreads();

    #pragma unroll
    for (int mt = 0; mt < 2; mt++) {
        int r = m0 + wm * 32 + mt * 16 + (lane >> 2);
        #pragma unroll
        for (int nf = 0; nf < 4; nf++) {
            int nn = wn * 32 + nf * 8 + (lane & 3) * 2;
            float b0v = sbias[nn], b1v = sbias[nn + 1];
            int n = n0 + nn;
            g_xp[(size_t)r * G4 + n]           = acc[mt][nf][0] + b0v;
            g_xp[(size_t)r * G4 + n + 1]       = acc[mt][nf][1] + b1v;
            g_xp[(size_t)(r + 8) * G4 + n]     = acc[mt][nf][2] + b0v;
            g_xp[(size_t)(r + 8) * G4 + n + 1] = acc[mt][nf][3] + b1v;
        }
    }
}

// ---------------- combined LSTM step (both layers pipelined) ----------------
// grid (32, 4, 2). z=0: layer0 step t=li; z=1: layer1 step t=li-1 (K=1024 fused
// Wih1@h0_t + Whh1@h1_{t-1}). 2-stage cp.async, 2 CTAs/SM.
__global__ void __launch_bounds__(256, 2) lstm_step2(int li,
                                                     const float* __restrict__ bih1,
                                                     const float* __restrict__ bhh1) {
    const int role = blockIdx.z;
    const int t = li - role;
    if (t < 0 || t >= T_STEPS) return;

    extern __shared__ char smem[];
    const uint32_t sb = smem_u32(smem);
    const int tid  = threadIdx.x;
    const int lane = tid & 31;
    const int warp = tid >> 5;
    const int wm = warp >> 2;
    const int wn = warp & 3;
    const int j0 = blockIdx.x * 16;
    const int b0 = blockIdx.y * 64;
    float* gst = (float*)(smem + S_G);

    // A sources per 16-chunk segment, B source, K-extent
    const __nv_bfloat16 *A0h, *A0l, *A1h, *A1l, *Bh, *Bl;
    int NC, Kw;
    if (role == 0) {
        NC = (t > 0) ? 16 : 0; Kw = 512;
        A0h = g_h_hi0 + (size_t)(t - 1) * NBH;  A0l = g_h_lo0 + (size_t)(t - 1) * NBH;
        A1h = A0h; A1l = A0l;
        Bh = g_whh_hi0; Bl = g_whh_lo0;
    } else {
        NC = (t > 0) ? 32 : 16; Kw = 1024;
        A0h = g_h_hi0 + (size_t)t * NBH;        A0l = g_h_lo0 + (size_t)t * NBH;
        A1h = g_h_hi1 + (size_t)(t - 1) * NBH;  A1l = g_h_lo1 + (size_t)(t - 1) * NBH;
        Bh = g_w1c_hi; Bl = g_w1c_lo;
    }

    float acc[2][2][4] = {};

    const int lrow = tid >> 2;
    const int lseg = (tid & 3) * 8;
    const int browg = (lrow >> 4) * H + j0 + (lrow & 15);

    const int acol = (lane >> 4) * 8;
    const int arow_f = wm * 32 + (lane & 15);
    const int brow_f = wn * 16 + ((lane >> 4) << 3) + (lane & 7);
    const int bcol_f = ((lane >> 3) & 1) * 8;

    if (NC > 0) {
        auto prefetch = [&](int c, int st) {
            const __nv_bfloat16* ah = (c < 16) ? A0h : A1h;
            const __nv_bfloat16* al = (c < 16) ? A0l : A1l;
            int ccol = (c & 15) << 5;
            size_t ga = (size_t)(b0 + lrow) * H + ccol + lseg;
            size_t gb = (size_t)browg * Kw + (c << 5) + lseg;
            uint32_t so = (uint32_t)(lrow * LDT + lseg) * 2;
            cpa16(sb + S_A(st,0) + so, ah + ga);
            cpa16(sb + S_A(st,1) + so, al + ga);
            cpa16(sb + S_B(st,0) + so, Bh + gb);
            cpa16(sb + S_B(st,1) + so, Bl + gb);
            cpa_commit();
        };

        prefetch(0, 0);

        for (int c = 0; c < NC; c++) {
            const int st = c & 1;
            cpa_wait0();
            __syncthreads();
            if (c + 1 < NC) prefetch(c + 1, (c + 1) & 1);

            const uint32_t aH = sb + S_A(st,0) + (uint32_t)(arow_f * LDT + acol) * 2;
            const uint32_t aL = sb + S_A(st,1) + (uint32_t)(arow_f * LDT + acol) * 2;
            const uint32_t bH = sb + S_B(st,0) + (uint32_t)(brow_f * LDT + bcol_f) * 2;
            const uint32_t bL = sb + S_B(st,1) + (uint32_t)(brow_f * LDT + bcol_f) * 2;

            #pragma unroll
            for (int kk = 0; kk < 2; kk++) {
                const uint32_t koff = (uint32_t)(kk * 32);
                uint32_t a_hi[2][4], a_lo[2][4];
                #pragma unroll
                for (int mt = 0; mt < 2; mt++) {
                    ldm_x4(a_hi[mt][0], a_hi[mt][1], a_hi[mt][2], a_hi[mt][3],
                           aH + mt * 16 * LDT * 2 + koff);
                    ldm_x4(a_lo[mt][0], a_lo[mt][1], a_lo[mt][2], a_lo[mt][3],
                           aL + mt * 16 * LDT * 2 + koff);
                }
                uint32_t b_hi[4], b_lo[4];
                ldm_x4(b_hi[0], b_hi[1], b_hi[2], b_hi[3], bH + koff);
                ldm_x4(b_lo[0], b_lo[1], b_lo[2], b_lo[3], bL + koff);
                #pragma unroll
                for (int mt = 0; mt < 2; mt++)
                    #pragma unroll
                    for (int nt = 0; nt < 2; nt++) {
                        mma_bf16(acc[mt][nt], a_hi[mt], b_hi[nt * 2], b_hi[nt * 2 + 1]);
                        mma_bf16(acc[mt][nt], a_hi[mt], b_lo[nt * 2], b_lo[nt * 2 + 1]);
                        mma_bf16(acc[mt][nt], a_lo[mt], b_hi[nt * 2], b_hi[nt * 2 + 1]);
                    }
            }
        }
    }

    // stage gates
    #pragma unroll
    for (int mt = 0; mt < 2; mt++) {
        int r = wm * 32 + mt * 16 + (lane >> 2);
        #pragma unroll
        for (int nt = 0; nt < 2; nt++) {
            int cc = wn * 16 + nt * 8 + (lane & 3) * 2;
            gst[r * GST + cc]           = acc[mt][nt][0];
            gst[r * GST + cc + 1]       = acc[mt][nt][1];
            gst[(r + 8) * GST + cc]     = acc[mt][nt][2];
            gst[(r + 8) * GST + cc + 1] = acc[mt][nt][3];
        }
    }
    __syncthreads();

    // fused cell update
    {
        __nv_bfloat16* ho_hi = (role ? g_h_hi1 : g_h_hi0) + (size_t)t * NBH;
        __nv_bfloat16* ho_lo = (role ? g_h_lo1 : g_h_lo0) + (size_t)t * NBH;
        float* cst = role ? g_c1 : g_c0;

        int bb = tid >> 2, jg = (tid & 3) * 4;
        int b  = b0 + bb;
        float xi[4], xf[4], xgt[4], xo[4];
        if (role == 0) {
            const float* xr = g_xp + (size_t)t * NB * G4 + (size_t)b * G4 + j0 + jg;
            *(float4*)xi  = *(const float4*)(xr + 0 * H);
            *(float4*)xf  = *(const float4*)(xr + 1 * H);
            *(float4*)xgt = *(const float4*)(xr + 2 * H);
            *(float4*)xo  = *(const float4*)(xr + 3 * H);
        } else {
            #pragma unroll
            for (int q = 0; q < 4; q++) {
                int n = j0 + jg + q;
                xi[q]  = bih1[n]           + bhh1[n];
                xf[q]  = bih1[H + n]       + bhh1[H + n];
                xgt[q] = bih1[2 * H + n]   + bhh1[2 * H + n];
                xo[q]  = bih1[3 * H + n]   + bhh1[3 * H + n];
            }
        }
        const float* g = &gst[bb * GST];
        size_t idx = (size_t)b * H + j0 + jg;
        float4 cold = *(const float4*)(cst + idx);
        const float* cop = (const float*)&cold;
        float cn[4], hv[4];
        __nv_bfloat16 hhv[4], hlv[4];
        const bool wbase = (role == 1) && (t == T_STEPS - 1);
        #pragma unroll
        for (int q = 0; q < 4; q++) {
            float gi = g[jg + q]      + xi[q];
            float gf = g[16 + jg + q] + xf[q];
            float gg = g[32 + jg + q] + xgt[q];
            float go = g[48 + jg + q] + xo[q];
            float iv = sigf(gi), fv = sigf(gf), gv = tanhf(gg), ov = sigf(go);
            cn[q] = fv * cop[q] + iv * gv;
            hv[q] = ov * tanhf(cn[q]);
            hhv[q] = __float2bfloat16(hv[q]);
            hlv[q] = __float2bfloat16(hv[q] - __bfloat162float(hhv[q]));
        }
        *(float4*)(cst + idx) = *(float4*)cn;
        *(uint2*)&ho_hi[idx] = *(uint2*)hhv;
        *(uint2*)&ho_lo[idx] = *(uint2*)hlv;
        if (wbase) *(float4*)(g_base + idx) = *(float4*)hv;
    }
}

// ---------------- heads ----------------
__global__ void heads_kernel(const float* __restrict__ cls_W, const float* __restrict__ cls_b,
                             const float* __restrict__ bbox_W, const float* __restrict__ bbox_b,
                             float* __restrict__ out) {
    __shared__ float base[H];
    int b = blockIdx.x;
    const float* src = g_base + (size_t)b * H;
    for (int k = threadIdx.x; k < H; k += blockDim.x) base[k] = src[k];
    __syncthreads();
    for (int o = threadIdx.x; o < 42; o += blockDim.x) {
        const float* w = (o < 40) ? &cls_W[o * H] : &bbox_W[(o - 40) * H];
        float s = (o < 40) ? cls_b[o] : bbox_b[o - 40];
        #pragma unroll 8
        for (int k = 0; k < H; k++) s += base[k] * w[k];
        if (o < 40) out[b * 40 + o] = s;
        else        out[NB * 40 + b * 2 + (o - 40)] = s;
    }
}

extern "C" void kernel_launch(void* const* d_in, const int* in_sizes, int n_in,
                              void* d_out, int out_size) {
    const float* proposals = (const float*)d_in[2];
    const float* Wih0 = (const float*)d_in[4];
    const float* Whh0 = (const float*)d_in[5];
    const float* bih0 = (const float*)d_in[6];
    const float* bhh0 = (const float*)d_in[7];
    const float* Wih1 = (const float*)d_in[8];
    const float* Whh1 = (const float*)d_in[9];
    const float* bih1 = (const float*)d_in[10];
    const float* bhh1 = (const float*)d_in[11];
    const float* cls_W  = (const float*)d_in[12];
    const float* cls_b  = (const float*)d_in[13];
    const float* bbox_W = (const float*)d_in[14];
    const float* bbox_b = (const float*)d_in[15];
    float* out = (float*)d_out;

    cudaFuncSetAttribute(xproj_mma, cudaFuncAttributeMaxDynamicSharedMemorySize, XSM_TOTAL);
    cudaFuncSetAttribute(lstm_step2, cudaFuncAttributeMaxDynamicSharedMemorySize, SSM_TOTAL);

    zero_kernel<<<256, 256>>>(out, out_size);

    conv_w<<<(G4 * CIN + 255) / 256, 256>>>(Wih0, 0, G4 * CIN);
    conv_w<<<(G4 * H + 255) / 256, 256>>>(Whh0, 1, G4 * H);
    conv_w1<<<(G4 * 1024 + 255) / 256, 256>>>(Wih1, Whh1);
    conv_x<<<(T_STEPS * NB * CIN + 255) / 256, 256>>>(proposals);

    dim3 gx(G4 / XBN, (T_STEPS * NB) / XBM);   // (32, 400)
    dim3 gs(H / 16, NB / 64, 2);               // (32, 4, 2) = 256 CTAs

    xproj_mma<<<gx, 256, XSM_TOTAL>>>(CIN, bih0, bhh0);

    for (int i = 0; i <= T_STEPS; i++)
        lstm_step2<<<gs, 256, SSM_TOTAL>>>(i, bih1, bhh1);

    heads_kernel<<<NB, 64>>>(cls_W, cls_b, bbox_W, bbox_b, out);
}

// round 13
// speedup vs baseline: 1.1608x; 1.1179x over previous
#include <cuda_runtime.h>
#include <cuda_bf16.h>
#include <cstdint>
#include <math.h>

#define T_STEPS 200
#define NB      256
#define H       512
#define CIN     128
#define G4      2048
#define NBH     (NB*H)

// xproj tiling: 128x64, BK=32, 4 stages
#define XBM 128
#define XBN 64
#define LDT 40          // xproj smem row stride (bf16)
#define GST 72

// step kernel: K-chunk = 64, row stride 72 (144B; 8-row ldmatrix conflict-free)
#define SLDT 72
// stage = Ahi,Alo,Bhi,Blo each 64*72*2 = 9216 -> 36864/stage
#define S_A(s,h)  ((s)*36864 + (h)*9216)
#define S_B(s,h)  ((s)*36864 + 18432 + (h)*9216)
#define S_G       73728
#define SSM_TOTAL (73728 + 64*GST*4)          // 92160
// xproj smem (4-stage)
#define X_A(s,h)  ((s)*30720 + (h)*10240)
#define X_B(s,h)  ((s)*30720 + 20480 + (h)*5120)
#define XSM_TOTAL (4*30720)                   // 122880

// ---------------- device scratch ----------------
__device__ __nv_bfloat16 g_wih_hi0[G4*CIN], g_wih_lo0[G4*CIN];
__device__ __nv_bfloat16 g_whh_hi0[G4*H],   g_whh_lo0[G4*H];
__device__ __nv_bfloat16 g_w1c_hi[(size_t)G4*1024], g_w1c_lo[(size_t)G4*1024]; // [Wih1|Whh1]
__device__ __nv_bfloat16 g_h_hi0[(size_t)T_STEPS*NBH], g_h_lo0[(size_t)T_STEPS*NBH];
__device__ __nv_bfloat16 g_h_hi1[(size_t)T_STEPS*NBH], g_h_lo1[(size_t)T_STEPS*NBH];
__device__ __nv_bfloat16 g_x_hi[(size_t)T_STEPS*NB*CIN], g_x_lo[(size_t)T_STEPS*NB*CIN];
__device__ float g_xp[(size_t)T_STEPS*NB*G4];
__device__ float g_c0[NBH], g_c1[NBH];
__device__ float g_base[NBH];

// ---------------- helpers ----------------
__device__ __forceinline__ uint32_t smem_u32(const void* p) {
    return (uint32_t)__cvta_generic_to_shared(p);
}
__device__ __forceinline__ void ldm_x4(uint32_t& r0, uint32_t& r1, uint32_t& r2, uint32_t& r3,
                                       uint32_t addr) {
    asm volatile("ldmatrix.sync.aligned.m8n8.x4.shared.b16 {%0,%1,%2,%3}, [%4];"
                 : "=r"(r0), "=r"(r1), "=r"(r2), "=r"(r3) : "r"(addr));
}
__device__ __forceinline__ void mma_bf16(float* c, const uint32_t* a, uint32_t b0, uint32_t b1) {
    asm volatile("mma.sync.aligned.m16n8k16.row.col.f32.bf16.bf16.f32 "
                 "{%0,%1,%2,%3}, {%4,%5,%6,%7}, {%8,%9}, {%0,%1,%2,%3};"
                 : "+f"(c[0]), "+f"(c[1]), "+f"(c[2]), "+f"(c[3])
                 : "r"(a[0]), "r"(a[1]), "r"(a[2]), "r"(a[3]), "r"(b0), "r"(b1));
}
__device__ __forceinline__ void cpa16(uint32_t dst, const void* src) {
    asm volatile("cp.async.cg.shared.global [%0], [%1], 16;" :: "r"(dst), "l"(src));
}
__device__ __forceinline__ void cpa_commit() { asm volatile("cp.async.commit_group;"); }
__device__ __forceinline__ void cpa_wait0()  { asm volatile("cp.async.wait_group 0;"); }
__device__ __forceinline__ void cpa_wait1()  { asm volatile("cp.async.wait_group 1;"); }
__device__ __forceinline__ void cpa_wait2()  { asm volatile("cp.async.wait_group 2;"); }
__device__ __forceinline__ void cpa_wait_tail(int c, int NC) {
    if (c < NC - 2)      cpa_wait2();
    else if (c == NC - 2) cpa_wait1();
    else                  cpa_wait0();
}
__device__ __forceinline__ float sigf(float x) { return 1.f / (1.f + expf(-x)); }

// ---------------- init ----------------
__global__ void zero_kernel(float* __restrict__ out, int out_size) {
    int i = blockIdx.x * blockDim.x + threadIdx.x;
    int s = gridDim.x * blockDim.x;
    for (int k = i; k < out_size; k += s) out[k] = 0.f;
    for (int k = i; k < NBH; k += s) { g_c0[k] = 0.f; g_c1[k] = 0.f; }
}

// ---------------- fp32 -> bf16 hi/lo ----------------
__global__ void conv_w(const float* __restrict__ src, int which, int n) {
    int i = blockIdx.x * blockDim.x + threadIdx.x;
    if (i >= n) return;
    float v = src[i];
    __nv_bfloat16 h = __float2bfloat16(v);
    __nv_bfloat16 l = __float2bfloat16(v - __bfloat162float(h));
    if (which == 0) { g_wih_hi0[i] = h; g_wih_lo0[i] = l; }
    else            { g_whh_hi0[i] = h; g_whh_lo0[i] = l; }
}
__global__ void conv_w1(const float* __restrict__ Wih1, const float* __restrict__ Whh1) {
    int i = blockIdx.x * blockDim.x + threadIdx.x;
    if (i >= G4 * 1024) return;
    int r = i >> 10, k = i & 1023;
    float v = (k < 512) ? Wih1[(size_t)r * 512 + k] : Whh1[(size_t)r * 512 + (k - 512)];
    __nv_bfloat16 h = __float2bfloat16(v);
    g_w1c_hi[i] = h;
    g_w1c_lo[i] = __float2bfloat16(v - __bfloat162float(h));
}
__global__ void conv_x(const float* __restrict__ prop) {
    int i = blockIdx.x * blockDim.x + threadIdx.x;
    if (i >= T_STEPS * NB * CIN) return;
    int k = i & (CIN - 1);
    int m = i >> 7;
    int b = m & (NB - 1), t = m >> 8;
    float v = prop[((size_t)b * T_STEPS + t) * CIN + k];
    __nv_bfloat16 h = __float2bfloat16(v);
    g_x_hi[i] = h;
    g_x_lo[i] = __float2bfloat16(v - __bfloat162float(h));
}

// ---------------- xproj GEMM (layer 0 only): 128x64 tile, 4-stage -----------
__global__ void __launch_bounds__(256) xproj_mma(int K,
                                                 const float* __restrict__ bih,
                                                 const float* __restrict__ bhh) {
    extern __shared__ char smem[];
    __shared__ float sbias[XBN];
    const uint32_t sb = smem_u32(smem);
    const int tid  = threadIdx.x;
    const int lane = tid & 31;
    const int warp = tid >> 5;
    const int wm = warp & 3;
    const int wn = warp >> 2;

    const int m0 = blockIdx.y * XBM;
    const int n0 = blockIdx.x * XBN;
    const __nv_bfloat16* Aptr_hi = g_x_hi;
    const __nv_bfloat16* Aptr_lo = g_x_lo;
    const __nv_bfloat16* Bptr_hi = g_wih_hi0;
    const __nv_bfloat16* Bptr_lo = g_wih_lo0;
    if (tid < XBN) sbias[tid] = bih[n0 + tid] + bhh[n0 + tid];

    float acc[2][4][4] = {};
    const int NC = K >> 5;

    const int brow_ld = tid >> 2, bseg_ld = (tid & 3) * 8;
    const int acol = (lane >> 4) * 8;
    const int arow_f = wm * 32 + (lane & 15);
    const int brow_f = ((lane >> 4) << 3) + (lane & 7);
    const int bcol_f = ((lane >> 3) & 1) * 8;

    #pragma unroll
    for (int pc = 0; pc < 3; pc++) {
        if (pc < NC) {
            const int c0 = pc << 5;
            #pragma unroll
            for (int i = 0; i < 2; i++) {
                int idx = tid + i * 256; int r = idx >> 2, sg = (idx & 3) * 8;
                size_t ga = (size_t)(m0 + r) * K + c0 + sg;
                uint32_t so = (uint32_t)(r * LDT + sg) * 2;
                cpa16(sb + X_A(pc,0) + so, Aptr_hi + ga);
                cpa16(sb + X_A(pc,1) + so, Aptr_lo + ga);
            }
            size_t gb = (size_t)(n0 + brow_ld) * K + c0 + bseg_ld;
            uint32_t so = (uint32_t)(brow_ld * LDT + bseg_ld) * 2;
            cpa16(sb + X_B(pc,0) + so, Bptr_hi + gb);
            cpa16(sb + X_B(pc,1) + so, Bptr_lo + gb);
        }
        cpa_commit();
    }

    for (int c = 0; c < NC; c++) {
        const int st = c & 3;
        cpa_wait_tail(c, NC);
        __syncthreads();
        {
            const int ns = (c + 3) & 3;
            const int c0 = (c + 3) << 5;
            if (c + 3 < NC) {
                #pragma unroll
                for (int i = 0; i < 2; i++) {
                    int idx = tid + i * 256; int r = idx >> 2, sg = (idx & 3) * 8;
                    size_t ga = (size_t)(m0 + r) * K + c0 + sg;
                    uint32_t so = (uint32_t)(r * LDT + sg) * 2;
                    cpa16(sb + X_A(ns,0) + so, Aptr_hi + ga);
                    cpa16(sb + X_A(ns,1) + so, Aptr_lo + ga);
                }
                size_t gb = (size_t)(n0 + brow_ld) * K + c0 + bseg_ld;
                uint32_t so = (uint32_t)(brow_ld * LDT + bseg_ld) * 2;
                cpa16(sb + X_B(ns,0) + so, Bptr_hi + gb);
                cpa16(sb + X_B(ns,1) + so, Bptr_lo + gb);
            }
            cpa_commit();
        }

        const uint32_t aH = sb + X_A(st,0) + (uint32_t)(arow_f * LDT + acol) * 2;
        const uint32_t aL = sb + X_A(st,1) + (uint32_t)(arow_f * LDT + acol) * 2;
        const uint32_t bH0 = sb + X_B(st,0) + (uint32_t)((wn * 32 + brow_f) * LDT + bcol_f) * 2;
        const uint32_t bL0 = sb + X_B(st,1) + (uint32_t)((wn * 32 + brow_f) * LDT + bcol_f) * 2;

        #pragma unroll
        for (int kk = 0; kk < 2; kk++) {
            const uint32_t koff = (uint32_t)(kk * 32);
            uint32_t a_hi[2][4], a_lo[2][4];
            #pragma unroll
            for (int mt = 0; mt < 2; mt++) {
                ldm_x4(a_hi[mt][0], a_hi[mt][1], a_hi[mt][2], a_hi[mt][3],
                       aH + mt * 16 * LDT * 2 + koff);
                ldm_x4(a_lo[mt][0], a_lo[mt][1], a_lo[mt][2], a_lo[mt][3],
                       aL + mt * 16 * LDT * 2 + koff);
            }
            uint32_t b_hi[2][4], b_lo[2][4];
            #pragma unroll
            for (int nf2 = 0; nf2 < 2; nf2++) {
                ldm_x4(b_hi[nf2][0], b_hi[nf2][1], b_hi[nf2][2], b_hi[nf2][3],
                       bH0 + nf2 * 16 * LDT * 2 + koff);
                ldm_x4(b_lo[nf2][0], b_lo[nf2][1], b_lo[nf2][2], b_lo[nf2][3],
                       bL0 + nf2 * 16 * LDT * 2 + koff);
            }
            #pragma unroll
            for (int mt = 0; mt < 2; mt++)
                #pragma unroll
                for (int nf = 0; nf < 4; nf++) {
                    int n2 = nf >> 1, rp = (nf & 1) * 2;
                    mma_bf16(acc[mt][nf], a_hi[mt], b_hi[n2][rp], b_hi[n2][rp + 1]);
                    mma_bf16(acc[mt][nf], a_hi[mt], b_lo[n2][rp], b_lo[n2][rp + 1]);
                    mma_bf16(acc[mt][nf], a_lo[mt], b_hi[n2][rp], b_hi[n2][rp + 1]);
                }
        }
    }
    __syncthreads();

    #pragma unroll
    for (int mt = 0; mt < 2; mt++) {
        int r = m0 + wm * 32 + mt * 16 + (lane >> 2);
        #pragma unroll
        for (int nf = 0; nf < 4; nf++) {
            int nn = wn * 32 + nf * 8 + (lane & 3) * 2;
            float b0v = sbias[nn], b1v = sbias[nn + 1];
            int n = n0 + nn;
            g_xp[(size_t)r * G4 + n]           = acc[mt][nf][0] + b0v;
            g_xp[(size_t)r * G4 + n + 1]       = acc[mt][nf][1] + b1v;
            g_xp[(size_t)(r + 8) * G4 + n]     = acc[mt][nf][2] + b0v;
            g_xp[(size_t)(r + 8) * G4 + n + 1] = acc[mt][nf][3] + b1v;
        }
    }
}

// ---------------- combined LSTM step (both layers pipelined) ----------------
// grid (2, 32, 4): role = blockIdx.x (interleaved in bid for SM balance),
// j0 = blockIdx.y*16, b0 = blockIdx.z*64. K-chunk = 64, 2-stage.
__global__ void __launch_bounds__(256, 2) lstm_step2(int li,
                                                     const float* __restrict__ bih1,
                                                     const float* __restrict__ bhh1) {
    const int role = blockIdx.x;
    const int t = li - role;
    if (t < 0 || t >= T_STEPS) return;

    extern __shared__ char smem[];
    const uint32_t sb = smem_u32(smem);
    const int tid  = threadIdx.x;
    const int lane = tid & 31;
    const int warp = tid >> 5;
    const int wm = warp >> 2;
    const int wn = warp & 3;
    const int j0 = blockIdx.y * 16;
    const int b0 = blockIdx.z * 64;
    float* gst = (float*)(smem + S_G);

    const __nv_bfloat16 *A0h, *A0l, *A1h, *A1l, *Bh, *Bl;
    int NC, Kw;
    if (role == 0) {
        NC = (t > 0) ? 8 : 0; Kw = 512;
        A0h = g_h_hi0 + (size_t)(t - 1) * NBH;  A0l = g_h_lo0 + (size_t)(t - 1) * NBH;
        A1h = A0h; A1l = A0l;
        Bh = g_whh_hi0; Bl = g_whh_lo0;
    } else {
        NC = (t > 0) ? 16 : 8; Kw = 1024;
        A0h = g_h_hi0 + (size_t)t * NBH;        A0l = g_h_lo0 + (size_t)t * NBH;
        A1h = g_h_hi1 + (size_t)(t - 1) * NBH;  A1l = g_h_lo1 + (size_t)(t - 1) * NBH;
        Bh = g_w1c_hi; Bl = g_w1c_lo;
    }

    float acc[2][2][4] = {};

    const int acol = (lane >> 4) * 8;
    const int arow_f = wm * 32 + (lane & 15);
    const int brow_f = wn * 16 + ((lane >> 4) << 3) + (lane & 7);
    const int bcol_f = ((lane >> 3) & 1) * 8;

    if (NC > 0) {
        auto prefetch = [&](int c, int st) {
            const __nv_bfloat16* ah = (c < 8) ? A0h : A1h;
            const __nv_bfloat16* al = (c < 8) ? A0l : A1l;
            const int ccol = (c & 7) << 6;
            #pragma unroll
            for (int i = 0; i < 2; i++) {
                int unit = tid + i * 256;
                int r = unit >> 3, sg = (unit & 7) * 8;
                uint32_t so = (uint32_t)(r * SLDT + sg) * 2;
                size_t ga = (size_t)(b0 + r) * H + ccol + sg;
                cpa16(sb + S_A(st,0) + so, ah + ga);
                cpa16(sb + S_A(st,1) + so, al + ga);
                int wrow = (r >> 4) * H + j0 + (r & 15);
                size_t gb = (size_t)wrow * Kw + (c << 6) + sg;
                cpa16(sb + S_B(st,0) + so, Bh + gb);
                cpa16(sb + S_B(st,1) + so, Bl + gb);
            }
            cpa_commit();
        };

        prefetch(0, 0);

        for (int c = 0; c < NC; c++) {
            const int st = c & 1;
            cpa_wait0();
            __syncthreads();
            if (c + 1 < NC) prefetch(c + 1, (c + 1) & 1);

            const uint32_t aH = sb + S_A(st,0) + (uint32_t)(arow_f * SLDT + acol) * 2;
            const uint32_t aL = sb + S_A(st,1) + (uint32_t)(arow_f * SLDT + acol) * 2;
            const uint32_t bH = sb + S_B(st,0) + (uint32_t)(brow_f * SLDT + bcol_f) * 2;
            const uint32_t bL = sb + S_B(st,1) + (uint32_t)(brow_f * SLDT + bcol_f) * 2;

            #pragma unroll
            for (int kk = 0; kk < 4; kk++) {
                const uint32_t koff = (uint32_t)(kk * 32);
                uint32_t a_hi[2][4], a_lo[2][4];
                #pragma unroll
                for (int mt = 0; mt < 2; mt++) {
                    ldm_x4(a_hi[mt][0], a_hi[mt][1], a_hi[mt][2], a_hi[mt][3],
                           aH + mt * 16 * SLDT * 2 + koff);
                    ldm_x4(a_lo[mt][0], a_lo[mt][1], a_lo[mt][2], a_lo[mt][3],
                           aL + mt * 16 * SLDT * 2 + koff);
                }
                uint32_t b_hi[4], b_lo[4];
                ldm_x4(b_hi[0], b_hi[1], b_hi[2], b_hi[3], bH + koff);
                ldm_x4(b_lo[0], b_lo[1], b_lo[2], b_lo[3], bL + koff);
                #pragma unroll
                for (int mt = 0; mt < 2; mt++)
                    #pragma unroll
                    for (int nt = 0; nt < 2; nt++) {
                        mma_bf16(acc[mt][nt], a_hi[mt], b_hi[nt * 2], b_hi[nt * 2 + 1]);
                        mma_bf16(acc[mt][nt], a_hi[mt], b_lo[nt * 2], b_lo[nt * 2 + 1]);
                        mma_bf16(acc[mt][nt], a_lo[mt], b_hi[nt * 2], b_hi[nt * 2 + 1]);
                    }
            }
        }
    }

    // stage gates
    #pragma unroll
    for (int mt = 0; mt < 2; mt++) {
        int r = wm * 32 + mt * 16 + (lane >> 2);
        #pragma unroll
        for (int nt = 0; nt < 2; nt++) {
            int cc = wn * 16 + nt * 8 + (lane & 3) * 2;
            gst[r * GST + cc]           = acc[mt][nt][0];
            gst[r * GST + cc + 1]       = acc[mt][nt][1];
            gst[(r + 8) * GST + cc]     = acc[mt][nt][2];
            gst[(r + 8) * GST + cc + 1] = acc[mt][nt][3];
        }
    }
    __syncthreads();

    // fused cell update
    {
        __nv_bfloat16* ho_hi = (role ? g_h_hi1 : g_h_hi0) + (size_t)t * NBH;
        __nv_bfloat16* ho_lo = (role ? g_h_lo1 : g_h_lo0) + (size_t)t * NBH;
        float* cst = role ? g_c1 : g_c0;

        int bb = tid >> 2, jg = (tid & 3) * 4;
        int b  = b0 + bb;
        float xi[4], xf[4], xgt[4], xo[4];
        if (role == 0) {
            const float* xr = g_xp + (size_t)t * NB * G4 + (size_t)b * G4 + j0 + jg;
            *(float4*)xi  = *(const float4*)(xr + 0 * H);
            *(float4*)xf  = *(const float4*)(xr + 1 * H);
            *(float4*)xgt = *(const float4*)(xr + 2 * H);
            *(float4*)xo  = *(const float4*)(xr + 3 * H);
        } else {
            #pragma unroll
            for (int q = 0; q < 4; q++) {
                int n = j0 + jg + q;
                xi[q]  = bih1[n]           + bhh1[n];
                xf[q]  = bih1[H + n]       + bhh1[H + n];
                xgt[q] = bih1[2 * H + n]   + bhh1[2 * H + n];
                xo[q]  = bih1[3 * H + n]   + bhh1[3 * H + n];
            }
        }
        const float* g = &gst[bb * GST];
        size_t idx = (size_t)b * H + j0 + jg;
        float4 cold = *(const float4*)(cst + idx);
        const float* cop = (const float*)&cold;
        float cn[4], hv[4];
        __nv_bfloat16 hhv[4], hlv[4];
        const bool wbase = (role == 1) && (t == T_STEPS - 1);
        #pragma unroll
        for (int q = 0; q < 4; q++) {
            float gi = g[jg + q]      + xi[q];
            float gf = g[16 + jg + q] + xf[q];
            float gg = g[32 + jg + q] + xgt[q];
            float go = g[48 + jg + q] + xo[q];
            float iv = sigf(gi), fv = sigf(gf), gv = tanhf(gg), ov = sigf(go);
            cn[q] = fv * cop[q] + iv * gv;
            hv[q] = ov * tanhf(cn[q]);
            hhv[q] = __float2bfloat16(hv[q]);
            hlv[q] = __float2bfloat16(hv[q] - __bfloat162float(hhv[q]));
        }
        *(float4*)(cst + idx) = *(float4*)cn;
        *(uint2*)&ho_hi[idx] = *(uint2*)hhv;
        *(uint2*)&ho_lo[idx] = *(uint2*)hlv;
        if (wbase) *(float4*)(g_base + idx) = *(float4*)hv;
    }
}

// ---------------- heads ----------------
__global__ void heads_kernel(const float* __restrict__ cls_W, const float* __restrict__ cls_b,
                             const float* __restrict__ bbox_W, const float* __restrict__ bbox_b,
                             float* __restrict__ out) {
    __shared__ float base[H];
    int b = blockIdx.x;
    const float* src = g_base + (size_t)b * H;
    for (int k = threadIdx.x; k < H; k += blockDim.x) base[k] = src[k];
    __syncthreads();
    for (int o = threadIdx.x; o < 42; o += blockDim.x) {
        const float* w = (o < 40) ? &cls_W[o * H] : &bbox_W[(o - 40) * H];
        float s = (o < 40) ? cls_b[o] : bbox_b[o - 40];
        #pragma unroll 8
        for (int k = 0; k < H; k++) s += base[k] * w[k];
        if (o < 40) out[b * 40 + o] = s;
        else        out[NB * 40 + b * 2 + (o - 40)] = s;
    }
}

extern "C" void kernel_launch(void* const* d_in, const int* in_sizes, int n_in,
                              void* d_out, int out_size) {
    const float* proposals = (const float*)d_in[2];
    const float* Wih0 = (const float*)d_in[4];
    const float* Whh0 = (const float*)d_in[5];
    const float* bih0 = (const float*)d_in[6];
    const float* bhh0 = (const float*)d_in[7];
    const float* Wih1 = (const float*)d_in[8];
    const float* Whh1 = (const float*)d_in[9];
    const float* bih1 = (const float*)d_in[10];
    const float* bhh1 = (const float*)d_in[11];
    const float* cls_W  = (const float*)d_in[12];
    const float* cls_b  = (const float*)d_in[13];
    const float* bbox_W = (const float*)d_in[14];
    const float* bbox_b = (const float*)d_in[15];
    float* out = (float*)d_out;

    cudaFuncSetAttribute(xproj_mma, cudaFuncAttributeMaxDynamicSharedMemorySize, XSM_TOTAL);
    cudaFuncSetAttribute(lstm_step2, cudaFuncAttributeMaxDynamicSharedMemorySize, SSM_TOTAL);

    zero_kernel<<<256, 256>>>(out, out_size);

    conv_w<<<(G4 * CIN + 255) / 256, 256>>>(Wih0, 0, G4 * CIN);
    conv_w<<<(G4 * H + 255) / 256, 256>>>(Whh0, 1, G4 * H);
    conv_w1<<<(G4 * 1024 + 255) / 256, 256>>>(Wih1, Whh1);
    conv_x<<<(T_STEPS * NB * CIN + 255) / 256, 256>>>(proposals);

    dim3 gx(G4 / XBN, (T_STEPS * NB) / XBM);   // (32, 400)
    dim3 gs(2, H / 16, NB / 64);               // (2, 32, 4) role-interleaved

    xproj_mma<<<gx, 256, XSM_TOTAL>>>(CIN, bih0, bhh0);

    for (int i = 0; i <= T_STEPS; i++)
        lstm_step2<<<gs, 256, SSM_TOTAL>>>(i, bih1, bhh1);

    heads_kernel<<<NB, 64>>>(cls_W, cls_b, bbox_W, bbox_b, out);
}

// round 14
// speedup vs baseline: 1.4736x; 1.2695x over previous
#include <cuda_runtime.h>
#include <cuda_bf16.h>
#include <cuda_fp16.h>
#include <cstdint>
#include <math.h>

#define T_STEPS 200
#define NB      256
#define H       512
#define CIN     128
#define G4      2048
#define NBH     (NB*H)

// xproj tiling: 128x64, BK=32, 4 stages (bf16 3-product, unchanged)
#define XBM 128
#define XBN 64
#define LDT 40
#define GST 72

// step kernel: fp16 2-product, K-chunk 64, 3 stages
#define SLDT 72                               // row stride (16-bit elems), 144B
#define SST  27648                            // stage = A(9216) + Bhi(9216) + Blo(9216)
#define S3_A(s)   ((s)*SST)
#define S3_BH(s)  ((s)*SST + 9216)
#define S3_BL(s)  ((s)*SST + 18432)
#define S_G3      (3*SST)                     // 82944
#define SSM_TOTAL (S_G3 + 64*GST*4)           // 101376

#define X_A(s,h)  ((s)*30720 + (h)*10240)
#define X_B(s,h)  ((s)*30720 + 20480 + (h)*5120)
#define XSM_TOTAL (4*30720)

#define INV2048f (1.0f/2048.0f)

// ---------------- device scratch ----------------
__device__ __nv_bfloat16 g_wih_hi0[G4*CIN], g_wih_lo0[G4*CIN];   // xproj weights (bf16)
__device__ __half g_whh_hi0[G4*H],  g_whh_lo0[G4*H];             // fp16 hi + scaled lo
__device__ __half g_w1c_hi[(size_t)G4*1024], g_w1c_lo[(size_t)G4*1024]; // [Wih1|Whh1]
__device__ __half g_h0[(size_t)T_STEPS*NBH];                     // fp16 hidden states
__device__ __half g_h1[(size_t)T_STEPS*NBH];
__device__ __half g_hz[NBH];                                     // stays zero
__device__ __nv_bfloat16 g_x_hi[(size_t)T_STEPS*NB*CIN], g_x_lo[(size_t)T_STEPS*NB*CIN];
__device__ float g_xp[(size_t)T_STEPS*NB*G4];
__device__ float g_c0[NBH], g_c1[NBH];
__device__ float g_base[NBH];

// ---------------- helpers ----------------
__device__ __forceinline__ uint32_t smem_u32(const void* p) {
    return (uint32_t)__cvta_generic_to_shared(p);
}
__device__ __forceinline__ void ldm_x4(uint32_t& r0, uint32_t& r1, uint32_t& r2, uint32_t& r3,
                                       uint32_t addr) {
    asm volatile("ldmatrix.sync.aligned.m8n8.x4.shared.b16 {%0,%1,%2,%3}, [%4];"
                 : "=r"(r0), "=r"(r1), "=r"(r2), "=r"(r3) : "r"(addr));
}
__device__ __forceinline__ void mma_bf16(float* c, const uint32_t* a, uint32_t b0, uint32_t b1) {
    asm volatile("mma.sync.aligned.m16n8k16.row.col.f32.bf16.bf16.f32 "
                 "{%0,%1,%2,%3}, {%4,%5,%6,%7}, {%8,%9}, {%0,%1,%2,%3};"
                 : "+f"(c[0]), "+f"(c[1]), "+f"(c[2]), "+f"(c[3])
                 : "r"(a[0]), "r"(a[1]), "r"(a[2]), "r"(a[3]), "r"(b0), "r"(b1));
}
__device__ __forceinline__ void mma_f16(float* c, const uint32_t* a, uint32_t b0, uint32_t b1) {
    asm volatile("mma.sync.aligned.m16n8k16.row.col.f32.f16.f16.f32 "
                 "{%0,%1,%2,%3}, {%4,%5,%6,%7}, {%8,%9}, {%0,%1,%2,%3};"
                 : "+f"(c[0]), "+f"(c[1]), "+f"(c[2]), "+f"(c[3])
                 : "r"(a[0]), "r"(a[1]), "r"(a[2]), "r"(a[3]), "r"(b0), "r"(b1));
}
__device__ __forceinline__ void cpa16(uint32_t dst, const void* src) {
    asm volatile("cp.async.cg.shared.global [%0], [%1], 16;" :: "r"(dst), "l"(src));
}
__device__ __forceinline__ void cpa_commit() { asm volatile("cp.async.commit_group;"); }
__device__ __forceinline__ void cpa_wait0()  { asm volatile("cp.async.wait_group 0;"); }
__device__ __forceinline__ void cpa_wait1()  { asm volatile("cp.async.wait_group 1;"); }
__device__ __forceinline__ void cpa_wait2()  { asm volatile("cp.async.wait_group 2;"); }
__device__ __forceinline__ void cpa_wait_tail(int c, int NC) {
    if (c < NC - 2)      cpa_wait2();
    else if (c == NC - 2) cpa_wait1();
    else                  cpa_wait0();
}
__device__ __forceinline__ float sigf(float x) { return 1.f / (1.f + expf(-x)); }

// ---------------- init ----------------
__global__ void zero_kernel(float* __restrict__ out, int out_size) {
    int i = blockIdx.x * blockDim.x + threadIdx.x;
    int s = gridDim.x * blockDim.x;
    for (int k = i; k < out_size; k += s) out[k] = 0.f;
    for (int k = i; k < NBH; k += s) { g_c0[k] = 0.f; g_c1[k] = 0.f; }
}

// ---------------- weight/input conversions ----------------
// xproj weights: bf16 hi/lo (unchanged)
__global__ void conv_wih0(const float* __restrict__ src) {
    int i = blockIdx.x * blockDim.x + threadIdx.x;
    if (i >= G4 * CIN) return;
    float v = src[i];
    __nv_bfloat16 h = __float2bfloat16(v);
    g_wih_hi0[i] = h;
    g_wih_lo0[i] = __float2bfloat16(v - __bfloat162float(h));
}
// recurrence weights: fp16 hi + scaled lo
__global__ void conv_whh0(const float* __restrict__ src) {
    int i = blockIdx.x * blockDim.x + threadIdx.x;
    if (i >= G4 * H) return;
    float v = src[i];
    __half h = __float2half(v);
    g_whh_hi0[i] = h;
    g_whh_lo0[i] = __float2half((v - __half2float(h)) * 2048.0f);
}
__global__ void conv_w1(const float* __restrict__ Wih1, const float* __restrict__ Whh1) {
    int i = blockIdx.x * blockDim.x + threadIdx.x;
    if (i >= G4 * 1024) return;
    int r = i >> 10, k = i & 1023;
    float v = (k < 512) ? Wih1[(size_t)r * 512 + k] : Whh1[(size_t)r * 512 + (k - 512)];
    __half h = __float2half(v);
    g_w1c_hi[i] = h;
    g_w1c_lo[i] = __float2half((v - __half2float(h)) * 2048.0f);
}
__global__ void conv_x(const float* __restrict__ prop) {
    int i = blockIdx.x * blockDim.x + threadIdx.x;
    if (i >= T_STEPS * NB * CIN) return;
    int k = i & (CIN - 1);
    int m = i >> 7;
    int b = m & (NB - 1), t = m >> 8;
    float v = prop[((size_t)b * T_STEPS + t) * CIN + k];
    __nv_bfloat16 h = __float2bfloat16(v);
    g_x_hi[i] = h;
    g_x_lo[i] = __float2bfloat16(v - __bfloat162float(h));
}

// ---------------- xproj GEMM (layer 0 only, bf16 3-product): unchanged ------
__global__ void __launch_bounds__(256) xproj_mma(int K,
                                                 const float* __restrict__ bih,
                                                 const float* __restrict__ bhh) {
    extern __shared__ char smem[];
    __shared__ float sbias[XBN];
    const uint32_t sb = smem_u32(smem);
    const int tid  = threadIdx.x;
    const int lane = tid & 31;
    const int warp = tid >> 5;
    const int wm = warp & 3;
    const int wn = warp >> 2;

    const int m0 = blockIdx.y * XBM;
    const int n0 = blockIdx.x * XBN;
    const __nv_bfloat16* Aptr_hi = g_x_hi;
    const __nv_bfloat16* Aptr_lo = g_x_lo;
    const __nv_bfloat16* Bptr_hi = g_wih_hi0;
    const __nv_bfloat16* Bptr_lo = g_wih_lo0;
    if (tid < XBN) sbias[tid] = bih[n0 + tid] + bhh[n0 + tid];

    float acc[2][4][4] = {};
    const int NC = K >> 5;

    const int brow_ld = tid >> 2, bseg_ld = (tid & 3) * 8;
    const int acol = (lane >> 4) * 8;
    const int arow_f = wm * 32 + (lane & 15);
    const int brow_f = ((lane >> 4) << 3) + (lane & 7);
    const int bcol_f = ((lane >> 3) & 1) * 8;

    #pragma unroll
    for (int pc = 0; pc < 3; pc++) {
        if (pc < NC) {
            const int c0 = pc << 5;
            #pragma unroll
            for (int i = 0; i < 2; i++) {
                int idx = tid + i * 256; int r = idx >> 2, sg = (idx & 3) * 8;
                size_t ga = (size_t)(m0 + r) * K + c0 + sg;
                uint32_t so = (uint32_t)(r * LDT + sg) * 2;
                cpa16(sb + X_A(pc,0) + so, Aptr_hi + ga);
                cpa16(sb + X_A(pc,1) + so, Aptr_lo + ga);
            }
            size_t gb = (size_t)(n0 + brow_ld) * K + c0 + bseg_ld;
            uint32_t so = (uint32_t)(brow_ld * LDT + bseg_ld) * 2;
            cpa16(sb + X_B(pc,0) + so, Bptr_hi + gb);
            cpa16(sb + X_B(pc,1) + so, Bptr_lo + gb);
        }
        cpa_commit();
    }

    for (int c = 0; c < NC; c++) {
        const int st = c & 3;
        cpa_wait_tail(c, NC);
        __syncthreads();
        {
            const int ns = (c + 3) & 3;
            const int c0 = (c + 3) << 5;
            if (c + 3 < NC) {
                #pragma unroll
                for (int i = 0; i < 2; i++) {
                    int idx = tid + i * 256; int r = idx >> 2, sg = (idx & 3) * 8;
                    size_t ga = (size_t)(m0 + r) * K + c0 + sg;
                    uint32_t so = (uint32_t)(r * LDT + sg) * 2;
                    cpa16(sb + X_A(ns,0) + so, Aptr_hi + ga);
                    cpa16(sb + X_A(ns,1) + so, Aptr_lo + ga);
                }
                size_t gb = (size_t)(n0 + brow_ld) * K + c0 + bseg_ld;
                uint32_t so = (uint32_t)(brow_ld * LDT + bseg_ld) * 2;
                cpa16(sb + X_B(ns,0) + so, Bptr_hi + gb);
                cpa16(sb + X_B(ns,1) + so, Bptr_lo + gb);
            }
            cpa_commit();
        }

        const uint32_t aH = sb + X_A(st,0) + (uint32_t)(arow_f * LDT + acol) * 2;
        const uint32_t aL = sb + X_A(st,1) + (uint32_t)(arow_f * LDT + acol) * 2;
        const uint32_t bH0 = sb + X_B(st,0) + (uint32_t)((wn * 32 + brow_f) * LDT + bcol_f) * 2;
        const uint32_t bL0 = sb + X_B(st,1) + (uint32_t)((wn * 32 + brow_f) * LDT + bcol_f) * 2;

        #pragma unroll
        for (int kk = 0; kk < 2; kk++) {
            const uint32_t koff = (uint32_t)(kk * 32);
            uint32_t a_hi[2][4], a_lo[2][4];
            #pragma unroll
            for (int mt = 0; mt < 2; mt++) {
                ldm_x4(a_hi[mt][0], a_hi[mt][1], a_hi[mt][2], a_hi[mt][3],
                       aH + mt * 16 * LDT * 2 + koff);
                ldm_x4(a_lo[mt][0], a_lo[mt][1], a_lo[mt][2], a_lo[mt][3],
                       aL + mt * 16 * LDT * 2 + koff);
            }
            uint32_t b_hi[2][4], b_lo[2][4];
            #pragma unroll
            for (int nf2 = 0; nf2 < 2; nf2++) {
                ldm_x4(b_hi[nf2][0], b_hi[nf2][1], b_hi[nf2][2], b_hi[nf2][3],
                       bH0 + nf2 * 16 * LDT * 2 + koff);
                ldm_x4(b_lo[nf2][0], b_lo[nf2][1], b_lo[nf2][2], b_lo[nf2][3],
                       bL0 + nf2 * 16 * LDT * 2 + koff);
            }
            #pragma unroll
            for (int mt = 0; mt < 2; mt++)
                #pragma unroll
                for (int nf = 0; nf < 4; nf++) {
                    int n2 = nf >> 1, rp = (nf & 1) * 2;
                    mma_bf16(acc[mt][nf], a_hi[mt], b_hi[n2][rp], b_hi[n2][rp + 1]);
                    mma_bf16(acc[mt][nf], a_hi[mt], b_lo[n2][rp], b_lo[n2][rp + 1]);
                    mma_bf16(acc[mt][nf], a_lo[mt], b_hi[n2][rp], b_hi[n2][rp + 1]);
                }
        }
    }
    __syncthreads();

    #pragma unroll
    for (int mt = 0; mt < 2; mt++) {
        int r = m0 + wm * 32 + mt * 16 + (lane >> 2);
        #pragma unroll
        for (int nf = 0; nf < 4; nf++) {
            int nn = wn * 32 + nf * 8 + (lane & 3) * 2;
            float b0v = sbias[nn], b1v = sbias[nn + 1];
            int n = n0 + nn;
            g_xp[(size_t)r * G4 + n]           = acc[mt][nf][0] + b0v;
            g_xp[(size_t)r * G4 + n + 1]       = acc[mt][nf][1] + b1v;
            g_xp[(size_t)(r + 8) * G4 + n]     = acc[mt][nf][2] + b0v;
            g_xp[(size_t)(r + 8) * G4 + n + 1] = acc[mt][nf][3] + b1v;
        }
    }
}

// ---------------- combined LSTM step: fp16 2-product, 3-stage ---------------
// grid (2, 32, 4): role = blockIdx.x, j0 = blockIdx.y*16, b0 = blockIdx.z*64
__global__ void __launch_bounds__(256, 2) lstm_step2(int li,
                                                     const float* __restrict__ bih1,
                                                     const float* __restrict__ bhh1) {
    const int role = blockIdx.x;
    const int t = li - role;
    if (t < 0 || t >= T_STEPS) return;

    extern __shared__ char smem[];
    const uint32_t sb = smem_u32(smem);
    const int tid  = threadIdx.x;
    const int lane = tid & 31;
    const int warp = tid >> 5;
    const int wm = warp >> 2;
    const int wn = warp & 3;
    const int j0 = blockIdx.y * 16;
    const int b0 = blockIdx.z * 64;
    float* gst = (float*)(smem + S_G3);

    const __half *A0, *A1, *Bh, *Bl;
    int NC, Kw;
    if (role == 0) {
        NC = (t > 0) ? 8 : 0; Kw = 512;
        A0 = (t > 0) ? g_h0 + (size_t)(t - 1) * NBH : g_hz;
        A1 = A0;
        Bh = g_whh_hi0; Bl = g_whh_lo0;
    } else {
        NC = (t > 0) ? 16 : 8; Kw = 1024;
        A0 = g_h0 + (size_t)t * NBH;
        A1 = (t > 0) ? g_h1 + (size_t)(t - 1) * NBH : g_hz;
        Bh = g_w1c_hi; Bl = g_w1c_lo;
    }

    float acch[2][2][4] = {};
    float accl[2][2][4] = {};

    const int acol = (lane >> 4) * 8;
    const int arow_f = wm * 32 + (lane & 15);
    const int brow_f = wn * 16 + ((lane >> 4) << 3) + (lane & 7);
    const int bcol_f = ((lane >> 3) & 1) * 8;

    if (NC > 0) {
        auto prefetch = [&](int c) {
            const int st = c % 3;
            const __half* ap = (c < 8) ? A0 : A1;
            const int ccol = (c & 7) << 6;
            #pragma unroll
            for (int i = 0; i < 2; i++) {
                int unit = tid + i * 256;
                int r = unit >> 3, sg = (unit & 7) * 8;
                uint32_t so = (uint32_t)(r * SLDT + sg) * 2;
                size_t ga = (size_t)(b0 + r) * H + ccol + sg;
                cpa16(sb + S3_A(st) + so, ap + ga);
                int wrow = (r >> 4) * H + j0 + (r & 15);
                size_t gb = (size_t)wrow * Kw + (c << 6) + sg;
                cpa16(sb + S3_BH(st) + so, Bh + gb);
                cpa16(sb + S3_BL(st) + so, Bl + gb);
            }
            cpa_commit();
        };

        prefetch(0);
        if (NC > 1) prefetch(1);

        for (int c = 0; c < NC; c++) {
            const int st = c % 3;
            if (c < NC - 1) cpa_wait1(); else cpa_wait0();
            __syncthreads();
            if (c + 2 < NC) prefetch(c + 2);

            const uint32_t aS = sb + S3_A(st)  + (uint32_t)(arow_f * SLDT + acol) * 2;
            const uint32_t bH = sb + S3_BH(st) + (uint32_t)(brow_f * SLDT + bcol_f) * 2;
            const uint32_t bL = sb + S3_BL(st) + (uint32_t)(brow_f * SLDT + bcol_f) * 2;

            #pragma unroll
            for (int kk = 0; kk < 4; kk++) {
                const uint32_t koff = (uint32_t)(kk * 32);
                uint32_t a[2][4];
                #pragma unroll
                for (int mt = 0; mt < 2; mt++)
                    ldm_x4(a[mt][0], a[mt][1], a[mt][2], a[mt][3],
                           aS + mt * 16 * SLDT * 2 + koff);
                uint32_t b_hi[4], b_lo[4];
                ldm_x4(b_hi[0], b_hi[1], b_hi[2], b_hi[3], bH + koff);
                ldm_x4(b_lo[0], b_lo[1], b_lo[2], b_lo[3], bL + koff);
                #pragma unroll
                for (int mt = 0; mt < 2; mt++)
                    #pragma unroll
                    for (int nt = 0; nt < 2; nt++) {
                        mma_f16(acch[mt][nt], a[mt], b_hi[nt * 2], b_hi[nt * 2 + 1]);
                        mma_f16(accl[mt][nt], a[mt], b_lo[nt * 2], b_lo[nt * 2 + 1]);
                    }
            }
        }
    }

    // stage gates (combine hi + lo/2048)
    #pragma unroll
    for (int mt = 0; mt < 2; mt++) {
        int r = wm * 32 + mt * 16 + (lane >> 2);
        #pragma unroll
        for (int nt = 0; nt < 2; nt++) {
            int cc = wn * 16 + nt * 8 + (lane & 3) * 2;
            gst[r * GST + cc]           = acch[mt][nt][0] + accl[mt][nt][0] * INV2048f;
            gst[r * GST + cc + 1]       = acch[mt][nt][1] + accl[mt][nt][1] * INV2048f;
            gst[(r + 8) * GST + cc]     = acch[mt][nt][2] + accl[mt][nt][2] * INV2048f;
            gst[(r + 8) * GST + cc + 1] = acch[mt][nt][3] + accl[mt][nt][3] * INV2048f;
        }
    }
    __syncthreads();

    // fused cell update
    {
        __half* ho = (role ? g_h1 : g_h0) + (size_t)t * NBH;
        float* cst = role ? g_c1 : g_c0;

        int bb = tid >> 2, jg = (tid & 3) * 4;
        int b  = b0 + bb;
        float xi[4], xf[4], xgt[4], xo[4];
        if (role == 0) {
            const float* xr = g_xp + (size_t)t * NB * G4 + (size_t)b * G4 + j0 + jg;
            *(float4*)xi  = *(const float4*)(xr + 0 * H);
            *(float4*)xf  = *(const float4*)(xr + 1 * H);
            *(float4*)xgt = *(const float4*)(xr + 2 * H);
            *(float4*)xo  = *(const float4*)(xr + 3 * H);
        } else {
            #pragma unroll
            for (int q = 0; q < 4; q++) {
                int n = j0 + jg + q;
                xi[q]  = bih1[n]           + bhh1[n];
                xf[q]  = bih1[H + n]       + bhh1[H + n];
                xgt[q] = bih1[2 * H + n]   + bhh1[2 * H + n];
                xo[q]  = bih1[3 * H + n]   + bhh1[3 * H + n];
            }
        }
        const float* g = &gst[bb * GST];
        size_t idx = (size_t)b * H + j0 + jg;
        float4 cold = *(const float4*)(cst + idx);
        const float* cop = (const float*)&cold;
        float cn[4], hv[4];
        __half hval[4];
        const bool wbase = (role == 1) && (t == T_STEPS - 1);
        #pragma unroll
        for (int q = 0; q < 4; q++) {
            float gi = g[jg + q]      + xi[q];
            float gf = g[16 + jg + q] + xf[q];
            float gg = g[32 + jg + q] + xgt[q];
            float go = g[48 + jg + q] + xo[q];
            float iv = sigf(gi), fv = sigf(gf), gv = tanhf(gg), ov = sigf(go);
            cn[q] = fv * cop[q] + iv * gv;
            hv[q] = ov * tanhf(cn[q]);
            hval[q] = __float2half(hv[q]);
        }
        *(float4*)(cst + idx) = *(float4*)cn;
        *(uint2*)&ho[idx] = *(uint2*)hval;
        if (wbase) *(float4*)(g_base + idx) = *(float4*)hv;
    }
}

// ---------------- heads ----------------
__global__ void heads_kernel(const float* __restrict__ cls_W, const float* __restrict__ cls_b,
                             const float* __restrict__ bbox_W, const float* __restrict__ bbox_b,
                             float* __restrict__ out) {
    __shared__ float base[H];
    int b = blockIdx.x;
    const float* src = g_base + (size_t)b * H;
    for (int k = threadIdx.x; k < H; k += blockDim.x) base[k] = src[k];
    __syncthreads();
    for (int o = threadIdx.x; o < 42; o += blockDim.x) {
        const float* w = (o < 40) ? &cls_W[o * H] : &bbox_W[(o - 40) * H];
        float s = (o < 40) ? cls_b[o] : bbox_b[o - 40];
        #pragma unroll 8
        for (int k = 0; k < H; k++) s += base[k] * w[k];
        if (o < 40) out[b * 40 + o] = s;
        else        out[NB * 40 + b * 2 + (o - 40)] = s;
    }
}

extern "C" void kernel_launch(void* const* d_in, const int* in_sizes, int n_in,
                              void* d_out, int out_size) {
    const float* proposals = (const float*)d_in[2];
    const float* Wih0 = (const float*)d_in[4];
    const float* Whh0 = (const float*)d_in[5];
    const float* bih0 = (const float*)d_in[6];
    const float* bhh0 = (const float*)d_in[7];
    const float* Wih1 = (const float*)d_in[8];
    const float* Whh1 = (const float*)d_in[9];
    const float* bih1 = (const float*)d_in[10];
    const float* bhh1 = (const float*)d_in[11];
    const float* cls_W  = (const float*)d_in[12];
    const float* cls_b  = (const float*)d_in[13];
    const float* bbox_W = (const float*)d_in[14];
    const float* bbox_b = (const float*)d_in[15];
    float* out = (float*)d_out;

    cudaFuncSetAttribute(xproj_mma, cudaFuncAttributeMaxDynamicSharedMemorySize, XSM_TOTAL);
    cudaFuncSetAttribute(lstm_step2, cudaFuncAttributeMaxDynamicSharedMemorySize, SSM_TOTAL);

    zero_kernel<<<256, 256>>>(out, out_size);

    conv_wih0<<<(G4 * CIN + 255) / 256, 256>>>(Wih0);
    conv_whh0<<<(G4 * H + 255) / 256, 256>>>(Whh0);
    conv_w1<<<(G4 * 1024 + 255) / 256, 256>>>(Wih1, Whh1);
    conv_x<<<(T_STEPS * NB * CIN + 255) / 256, 256>>>(proposals);

    dim3 gx(G4 / XBN, (T_STEPS * NB) / XBM);   // (32, 400)
    dim3 gs(2, H / 16, NB / 64);               // (2, 32, 4)

    xproj_mma<<<gx, 256, XSM_TOTAL>>>(CIN, bih0, bhh0);

    for (int i = 0; i <= T_STEPS; i++)
        lstm_step2<<<gs, 256, SSM_TOTAL>>>(i, bih1, bhh1);

    heads_kernel<<<NB, 64>>>(cls_W, cls_b, bbox_W, bbox_b, out);
}